// round 8
// baseline (speedup 1.0000x reference)
#include <cuda_runtime.h>
#include <cuda_fp16.h>
#include <cstdint>

// ---------------------------------------------------------------------------
// Problem constants
// ---------------------------------------------------------------------------
#define B_BATCH 16
#define N_NODES 256
#define NODE_DIM 512
#define COND_DIM 512
#define EDGE_DIM 128
#define E_TOT 262144
#define LN_EPS 1e-5f

#define NROWS (B_BATCH * N_NODES)   // 4096
#define M_G 64
#define G_TILES (NROWS / M_G)       // 64
#define FILM_TILES (E_TOT / 128)    // 2048

// Fused-gemm SMEM layout
#define GS_BN 0
#define GS_R0 1024
#define GS_R1 (GS_R0 + 64 * 528)          // 34816
#define SMEM_GEMM (GS_R1 + 256 * 272)     // 104448

// ---------------------------------------------------------------------------
// Device scratch
// ---------------------------------------------------------------------------
__device__ __align__(16) __half g_wn[EDGE_DIM * NODE_DIM];        // 128KB
__device__ __align__(16) __half g_wcat[2 * EDGE_DIM * EDGE_DIM];  // 64KB
__device__ float g_gb[B_BATCH * 2 * EDGE_DIM];                    // 16KB
__device__ __align__(16) float g_P[NROWS * 2 * EDGE_DIM];         // 4MB

// ---------------------------------------------------------------------------
// Helpers
// ---------------------------------------------------------------------------
#define GRID_DEP_TRIGGER() asm volatile("griddepcontrol.launch_dependents;")
#define GRID_DEP_WAIT()    asm volatile("griddepcontrol.wait;" ::: "memory")

__device__ __forceinline__ uint32_t smem_to_u32(const void* p) {
    uint32_t a;
    asm("{ .reg .u64 t; cvta.to.shared.u64 t, %1; cvt.u32.u64 %0, t; }"
        : "=r"(a) : "l"(p));
    return a;
}

#define LDSM_X4(r0, r1, r2, r3, addr) \
    asm volatile("ldmatrix.sync.aligned.m8n8.x4.shared.b16 {%0,%1,%2,%3}, [%4];" \
        : "=r"(r0), "=r"(r1), "=r"(r2), "=r"(r3) : "r"(addr))

#define MMA16816(c, a0, a1, a2, a3, b0, b1) \
    asm volatile("mma.sync.aligned.m16n8k16.row.col.f32.f16.f16.f32 " \
        "{%0,%1,%2,%3}, {%4,%5,%6,%7}, {%8,%9}, {%0,%1,%2,%3};" \
        : "+f"((c)[0]), "+f"((c)[1]), "+f"((c)[2]), "+f"((c)[3]) \
        : "r"(a0), "r"(a1), "r"(a2), "r"(a3), "r"(b0), "r"(b1))

__device__ __forceinline__ uint32_t pk2h(float a, float b) {
    __half2 h = __floats2half2_rn(a, b);
    return reinterpret_cast<uint32_t&>(h);
}

__device__ __forceinline__ float warp_red(float v) {
    #pragma unroll
    for (int o = 16; o; o >>= 1) v += __shfl_xor_sync(0xffffffffu, v, o);
    return v;
}

// ---------------------------------------------------------------------------
// Prep: g_wn (weight-normed, fp16), g_wcat (reordered w_film fp16), g_gb
// ---------------------------------------------------------------------------
__global__ void prep_kernel(const float* __restrict__ v_node, const float* __restrict__ g_node,
                            const float* __restrict__ w_film,
                            const float* __restrict__ v_cond, const float* __restrict__ g_cond,
                            const float* __restrict__ b_cond, const float* __restrict__ cond_feats) {
    GRID_DEP_TRIGGER();
    __shared__ float red[4];
    int blk = blockIdx.x, tid = threadIdx.x, lane = tid & 31, wid = tid >> 5;

    if (blk < 128) {
        int r = blk;
        float4 v4 = *(const float4*)(v_node + (size_t)r * NODE_DIM + tid * 4);
        float s = v4.x * v4.x + v4.y * v4.y + v4.z * v4.z + v4.w * v4.w;
        s = warp_red(s);
        if (lane == 0) red[wid] = s;
        __syncthreads();
        float scale = g_node[r] * rsqrtf(red[0] + red[1] + red[2] + red[3]);
        uint2 u;
        u.x = pk2h(v4.x * scale, v4.y * scale);
        u.y = pk2h(v4.z * scale, v4.w * scale);
        *(uint2*)(g_wn + (size_t)r * NODE_DIM + tid * 4) = u;
        float2 wf = *(const float2*)(w_film + (size_t)r * 256 + tid * 2);
        uint32_t h = pk2h(wf.x, wf.y);
        if (tid < 64)
            *(uint32_t*)(g_wcat + (size_t)r * 128 + tid * 2) = h;
        else
            *(uint32_t*)(g_wcat + (size_t)(128 + r) * 128 + tid * 2 - 128) = h;
    } else {
        int c = blk - 128;
        const float* vrow = v_cond + (size_t)c * COND_DIM;
        float4 v4 = *(const float4*)(vrow + tid * 4);
        float s = v4.x * v4.x + v4.y * v4.y + v4.z * v4.z + v4.w * v4.w;
        s = warp_red(s);
        if (lane == 0) red[wid] = s;
        __syncthreads();
        float scale = g_cond[c] * rsqrtf(red[0] + red[1] + red[2] + red[3]);
        float bc = b_cond[c];
        #pragma unroll
        for (int bb = 0; bb < 4; ++bb) {
            int b = wid * 4 + bb;
            const float* crow = cond_feats + (size_t)b * COND_DIM;
            float p = 0.f;
            #pragma unroll
            for (int t = 0; t < 4; ++t) {
                int k4 = (lane + t * 32) * 4;
                float4 cf = *(const float4*)(crow + k4);
                float4 vv = *(const float4*)(vrow + k4);
                p += cf.x * vv.x + cf.y * vv.y + cf.z * vv.z + cf.w * vv.w;
            }
            p = warp_red(p);
            if (lane == 0) g_gb[b * 2 * EDGE_DIM + c] = p * scale + bc;
        }
    }
}

// ---------------------------------------------------------------------------
// Fused GEMM (PDL secondary of prep, primary of film2)
// ---------------------------------------------------------------------------
__global__ void __launch_bounds__(256, 1)
gemm_kernel(const float* __restrict__ node_feats, const float* __restrict__ b_node) {
    GRID_DEP_TRIGGER();   // let film2 launch + run its prologue under us
    extern __shared__ char smem[];
    uint32_t sb = smem_to_u32(smem);
    int tid = threadIdx.x, wid = tid >> 5, lane = tid & 31;
    int tile = blockIdx.x;
    float* bn_s = (float*)(smem + GS_BN);
    if (tid < 128) bn_s[tid] = b_node[tid];

    const int m0 = (wid & 1) * 32;
    const int n1 = (wid >> 1) * 32;
    uint32_t aB1[2], bB1[2];
    #pragma unroll
    for (int mi = 0; mi < 2; ++mi)
        aB1[mi] = sb + GS_R0 + (m0 + mi * 16 + (lane & 15)) * 528 + ((lane >> 4) << 4);
    #pragma unroll
    for (int nb = 0; nb < 2; ++nb)
        bB1[nb] = sb + GS_R1 + (n1 + nb * 16 + ((lane >> 4) << 3) + (lane & 7)) * 528
                  + (((lane >> 3) & 1) << 4);

    float acc1[2][4][4];
    #pragma unroll
    for (int mi = 0; mi < 2; ++mi)
        #pragma unroll
        for (int ni = 0; ni < 4; ++ni)
            #pragma unroll
            for (int j = 0; j < 4; ++j) acc1[mi][ni][j] = 0.f;

    for (int p = 0; p < 2; ++p) {
        __syncthreads();
        // A: node_feats (input; independent of prep)
        for (int idx = tid; idx < 2048; idx += 256) {
            int r = idx >> 5, cc = idx & 31;
            const float* s = node_feats + (size_t)(tile * M_G + r) * NODE_DIM + p * 256 + cc * 8;
            float4 f0 = *(const float4*)s;
            float4 f1 = *(const float4*)(s + 4);
            uint4 u;
            u.x = pk2h(f0.x, f0.y); u.y = pk2h(f0.z, f0.w);
            u.z = pk2h(f1.x, f1.y); u.w = pk2h(f1.z, f1.w);
            *(uint4*)(smem + GS_R0 + r * 528 + cc * 16) = u;
        }
        if (p == 0) GRID_DEP_WAIT();   // g_wn/g_wcat valid after this
        // B: g_wn (prep output)
        for (int idx = tid; idx < 4096; idx += 256) {
            int r = idx >> 5, cc = idx & 31;
            const uint4 wv = *(const uint4*)(g_wn + (size_t)r * NODE_DIM + p * 256 + cc * 8);
            *(uint4*)(smem + GS_R1 + r * 528 + cc * 16) = wv;
        }
        __syncthreads();
        #pragma unroll 4
        for (int kk = 0; kk < 16; ++kk) {
            uint32_t a[2][4], bf[2][4];
            #pragma unroll
            for (int mi = 0; mi < 2; ++mi)
                LDSM_X4(a[mi][0], a[mi][1], a[mi][2], a[mi][3], aB1[mi] + kk * 32);
            #pragma unroll
            for (int nb = 0; nb < 2; ++nb)
                LDSM_X4(bf[nb][0], bf[nb][1], bf[nb][2], bf[nb][3], bB1[nb] + kk * 32);
            #pragma unroll
            for (int mi = 0; mi < 2; ++mi)
                #pragma unroll
                for (int ni = 0; ni < 4; ++ni)
                    MMA16816(acc1[mi][ni], a[mi][0], a[mi][1], a[mi][2], a[mi][3],
                             bf[ni >> 1][(ni & 1) * 2], bf[ni >> 1][(ni & 1) * 2 + 1]);
        }
    }
    __syncthreads();

    // nodes (relu+bias fp16) -> region0; wcat -> region1
    {
        int rb = m0 + (lane >> 2);
        int cb = n1 + 2 * (lane & 3);
        #pragma unroll
        for (int mi = 0; mi < 2; ++mi)
            #pragma unroll
            for (int ni = 0; ni < 4; ++ni) {
                int r = rb + mi * 16;
                int c = cb + ni * 8;
                float b0 = bn_s[c], b1 = bn_s[c + 1];
                *(uint32_t*)(smem + GS_R0 + r * 272 + c * 2) =
                    pk2h(fmaxf(acc1[mi][ni][0] + b0, 0.f), fmaxf(acc1[mi][ni][1] + b1, 0.f));
                *(uint32_t*)(smem + GS_R0 + (r + 8) * 272 + c * 2) =
                    pk2h(fmaxf(acc1[mi][ni][2] + b0, 0.f), fmaxf(acc1[mi][ni][3] + b1, 0.f));
            }
    }
    for (int idx = tid; idx < 4096; idx += 256) {
        int r = idx >> 4, cc = idx & 15;
        const uint4 wv = *(const uint4*)(g_wcat + (size_t)r * 128 + cc * 8);
        *(uint4*)(smem + GS_R1 + r * 272 + cc * 16) = wv;
    }
    __syncthreads();

    // phase 2: 64x256x128
    const int n2 = (wid >> 1) * 64;
    uint32_t aB2[2], bB2[4];
    #pragma unroll
    for (int mi = 0; mi < 2; ++mi)
        aB2[mi] = sb + GS_R0 + (m0 + mi * 16 + (lane & 15)) * 272 + ((lane >> 4) << 4);
    #pragma unroll
    for (int nb = 0; nb < 4; ++nb)
        bB2[nb] = sb + GS_R1 + (n2 + nb * 16 + ((lane >> 4) << 3) + (lane & 7)) * 272
                  + (((lane >> 3) & 1) << 4);

    float acc2[2][8][4];
    #pragma unroll
    for (int mi = 0; mi < 2; ++mi)
        #pragma unroll
        for (int ni = 0; ni < 8; ++ni)
            #pragma unroll
            for (int j = 0; j < 4; ++j) acc2[mi][ni][j] = 0.f;

    #pragma unroll 2
    for (int kk = 0; kk < 8; ++kk) {
        uint32_t a[2][4], bf[4][4];
        #pragma unroll
        for (int mi = 0; mi < 2; ++mi)
            LDSM_X4(a[mi][0], a[mi][1], a[mi][2], a[mi][3], aB2[mi] + kk * 32);
        #pragma unroll
        for (int nb = 0; nb < 4; ++nb)
            LDSM_X4(bf[nb][0], bf[nb][1], bf[nb][2], bf[nb][3], bB2[nb] + kk * 32);
        #pragma unroll
        for (int mi = 0; mi < 2; ++mi)
            #pragma unroll
            for (int ni = 0; ni < 8; ++ni)
                MMA16816(acc2[mi][ni], a[mi][0], a[mi][1], a[mi][2], a[mi][3],
                         bf[ni >> 1][(ni & 1) * 2], bf[ni >> 1][(ni & 1) * 2 + 1]);
    }

    {
        int rb = m0 + (lane >> 2);
        int cb = n2 + 2 * (lane & 3);
        #pragma unroll
        for (int mi = 0; mi < 2; ++mi)
            #pragma unroll
            for (int ni = 0; ni < 8; ++ni) {
                int r = tile * M_G + rb + mi * 16;
                int c = cb + ni * 8;
                *(float2*)(g_P + (size_t)r * 256 + c) =
                    make_float2(acc2[mi][ni][0], acc2[mi][ni][1]);
                *(float2*)(g_P + (size_t)(r + 8) * 256 + c) =
                    make_float2(acc2[mi][ni][2], acc2[mi][ni][3]);
            }
    }
}

// ---------------------------------------------------------------------------
// film2: 2 edges per warp, half-warp reductions; PDL secondary of gemm
// ---------------------------------------------------------------------------
__global__ void __launch_bounds__(256)
film2_kernel(const int* __restrict__ eidx32, const float* __restrict__ b_film,
             float* __restrict__ out) {
    __shared__ int rowA_s[128], rowB_s[128];
    __shared__ __align__(16) float gam_s[128], bet_s[128], bf_s[128];
    int tid = threadIdx.x, wid = tid >> 5, lane = tid & 31;
    int tile = blockIdx.x;

    // prologue: inputs only (runs under gemm)
    if (tid < 128) {
        int stride = (eidx32[1] == 0 && eidx32[3] == 0 && eidx32[5] == 0) ? 2 : 1;
        int ei = eidx32[(size_t)(tile * 128 + tid) * stride];
        rowA_s[tid] = ei >> 8;
        rowB_s[tid] = ((ei >> 16) << 8) | (ei & 255);
        bf_s[tid] = b_film[tid];
    }
    GRID_DEP_WAIT();   // g_P and g_gb valid after this
    if (tid < 128) {
        int batch = tile >> 7;
        gam_s[tid] = g_gb[batch * 2 * EDGE_DIM + tid] + 1.0f;
        bet_s[tid] = g_gb[batch * 2 * EDGE_DIM + EDGE_DIM + tid];
    }
    __syncthreads();

    int half = lane >> 4;   // which edge of the pair
    int hl = lane & 15;
    int c8 = hl * 8;
    float4 gam0 = *(const float4*)(gam_s + c8);
    float4 gam1 = *(const float4*)(gam_s + c8 + 4);
    float4 bet0 = *(const float4*)(bet_s + c8);
    float4 bet1 = *(const float4*)(bet_s + c8 + 4);
    float4 bf0  = *(const float4*)(bf_s + c8);
    float4 bf1  = *(const float4*)(bf_s + c8 + 4);

    #pragma unroll 4
    for (int k = 0; k < 8; ++k) {
        int e = (wid << 4) + k * 2 + half;
        int rA = rowA_s[e], rB = rowB_s[e];
        const float4* pa = (const float4*)(g_P + (size_t)rA * 256) + hl * 2;
        const float4* pb = (const float4*)(g_P + (size_t)rB * 256 + 128) + hl * 2;
        float4 u0 = __ldg(pa), u1 = __ldg(pa + 1);
        float4 v0 = __ldg(pb), v1 = __ldg(pb + 1);
        float x0 = u0.x + v0.x + bf0.x;
        float x1 = u0.y + v0.y + bf0.y;
        float x2 = u0.z + v0.z + bf0.z;
        float x3 = u0.w + v0.w + bf0.w;
        float x4 = u1.x + v1.x + bf1.x;
        float x5 = u1.y + v1.y + bf1.y;
        float x6 = u1.z + v1.z + bf1.z;
        float x7 = u1.w + v1.w + bf1.w;
        float s = x0 + x1 + x2 + x3 + x4 + x5 + x6 + x7;
        float q = x0 * x0 + x1 * x1 + x2 * x2 + x3 * x3
                + x4 * x4 + x5 * x5 + x6 * x6 + x7 * x7;
        #pragma unroll
        for (int o = 8; o; o >>= 1) {
            s += __shfl_xor_sync(0xffffffffu, s, o);
            q += __shfl_xor_sync(0xffffffffu, q, o);
        }
        float mu = s * (1.f / 128.f);
        float var = q * (1.f / 128.f) - mu * mu;
        float ri = rsqrtf(fmaxf(var, 0.f) + LN_EPS);
        float4 o0, o1;
        o0.x = fmaxf((x0 - mu) * ri * gam0.x + bet0.x, 0.f);
        o0.y = fmaxf((x1 - mu) * ri * gam0.y + bet0.y, 0.f);
        o0.z = fmaxf((x2 - mu) * ri * gam0.z + bet0.z, 0.f);
        o0.w = fmaxf((x3 - mu) * ri * gam0.w + bet0.w, 0.f);
        o1.x = fmaxf((x4 - mu) * ri * gam1.x + bet1.x, 0.f);
        o1.y = fmaxf((x5 - mu) * ri * gam1.y + bet1.y, 0.f);
        o1.z = fmaxf((x6 - mu) * ri * gam1.z + bet1.z, 0.f);
        o1.w = fmaxf((x7 - mu) * ri * gam1.w + bet1.w, 0.f);
        float4* op = (float4*)(out + ((size_t)tile * 128 + e) * EDGE_DIM) + hl * 2;
        __stcs(op, o0);
        __stcs(op + 1, o1);
    }
}

// ---------------------------------------------------------------------------
// Launch (PDL chain: prep -> gemm -> film2)
// ---------------------------------------------------------------------------
extern "C" void kernel_launch(void* const* d_in, const int* in_sizes, int n_in,
                              void* d_out, int out_size) {
    const float* node_feats = (const float*)d_in[0];
    const float* cond_feats = (const float*)d_in[1];
    const int*   eidx       = (const int*)d_in[2];
    const float* v_node     = (const float*)d_in[3];
    const float* g_node     = (const float*)d_in[4];
    const float* b_node     = (const float*)d_in[5];
    const float* v_cond     = (const float*)d_in[6];
    const float* g_cond     = (const float*)d_in[7];
    const float* b_cond     = (const float*)d_in[8];
    const float* w_film     = (const float*)d_in[9];
    const float* b_film     = (const float*)d_in[10];
    float* out = (float*)d_out;

    cudaFuncSetAttribute(gemm_kernel, cudaFuncAttributeMaxDynamicSharedMemorySize, SMEM_GEMM);

    prep_kernel<<<384, 128>>>(v_node, g_node, w_film, v_cond, g_cond, b_cond, cond_feats);

    cudaLaunchAttribute at[1];
    at[0].id = cudaLaunchAttributeProgrammaticStreamSerialization;
    at[0].val.programmaticStreamSerializationAllowed = 1;

    {
        cudaLaunchConfig_t cfg = {};
        cfg.gridDim = dim3(G_TILES);
        cfg.blockDim = dim3(256);
        cfg.dynamicSmemBytes = SMEM_GEMM;
        cfg.stream = 0;
        cfg.attrs = at;
        cfg.numAttrs = 1;
        cudaLaunchKernelEx(&cfg, gemm_kernel, node_feats, b_node);
    }
    {
        cudaLaunchConfig_t cfg = {};
        cfg.gridDim = dim3(FILM_TILES);
        cfg.blockDim = dim3(256);
        cfg.dynamicSmemBytes = 0;
        cfg.stream = 0;
        cfg.attrs = at;
        cfg.numAttrs = 1;
        cudaLaunchKernelEx(&cfg, film2_kernel, eidx, b_film, out);
    }
}

// round 12
// speedup vs baseline: 1.4023x; 1.4023x over previous
#include <cuda_runtime.h>
#include <cuda_fp16.h>
#include <cstdint>

// ---------------------------------------------------------------------------
// Problem constants
// ---------------------------------------------------------------------------
#define B_BATCH 16
#define N_NODES 256
#define NODE_DIM 512
#define COND_DIM 512
#define EDGE_DIM 128
#define E_TOT 262144
#define LN_EPS 1e-5f

#define NROWS (B_BATCH * N_NODES)   // 4096
#define M_G 64
#define G_TILES (NROWS / M_G)       // 64
#define FILM_TILES (E_TOT / 128)    // 2048

// Fused-gemm SMEM layout
#define GS_BN 0
#define GS_R0 1024
#define GS_R1 (GS_R0 + 64 * 528)          // 34816
#define SMEM_GEMM (GS_R1 + 256 * 272)     // 104448

// ---------------------------------------------------------------------------
// Device scratch
// ---------------------------------------------------------------------------
__device__ __align__(16) __half g_wn[EDGE_DIM * NODE_DIM];        // 128KB
__device__ __align__(16) __half g_wcat[2 * EDGE_DIM * EDGE_DIM];  // 64KB
__device__ float g_gb[B_BATCH * 2 * EDGE_DIM];                    // 16KB
__device__ __align__(16) __half g_P[NROWS * 2 * EDGE_DIM];        // 2MB fp16

// ---------------------------------------------------------------------------
// Helpers
// ---------------------------------------------------------------------------
#define GRID_DEP_TRIGGER() asm volatile("griddepcontrol.launch_dependents;")
#define GRID_DEP_WAIT()    asm volatile("griddepcontrol.wait;" ::: "memory")

__device__ __forceinline__ uint32_t smem_to_u32(const void* p) {
    uint32_t a;
    asm("{ .reg .u64 t; cvta.to.shared.u64 t, %1; cvt.u32.u64 %0, t; }"
        : "=r"(a) : "l"(p));
    return a;
}

#define LDSM_X4(r0, r1, r2, r3, addr) \
    asm volatile("ldmatrix.sync.aligned.m8n8.x4.shared.b16 {%0,%1,%2,%3}, [%4];" \
        : "=r"(r0), "=r"(r1), "=r"(r2), "=r"(r3) : "r"(addr))

#define MMA16816(c, a0, a1, a2, a3, b0, b1) \
    asm volatile("mma.sync.aligned.m16n8k16.row.col.f32.f16.f16.f32 " \
        "{%0,%1,%2,%3}, {%4,%5,%6,%7}, {%8,%9}, {%0,%1,%2,%3};" \
        : "+f"((c)[0]), "+f"((c)[1]), "+f"((c)[2]), "+f"((c)[3]) \
        : "r"(a0), "r"(a1), "r"(a2), "r"(a3), "r"(b0), "r"(b1))

__device__ __forceinline__ uint32_t pk2h(float a, float b) {
    __half2 h = __floats2half2_rn(a, b);
    return reinterpret_cast<uint32_t&>(h);
}

__device__ __forceinline__ float warp_red(float v) {
    #pragma unroll
    for (int o = 16; o; o >>= 1) v += __shfl_xor_sync(0xffffffffu, v, o);
    return v;
}

// ---------------------------------------------------------------------------
// Prep: g_wn (weight-normed, fp16), g_wcat (reordered w_film fp16), g_gb
// ---------------------------------------------------------------------------
__global__ void prep_kernel(const float* __restrict__ v_node, const float* __restrict__ g_node,
                            const float* __restrict__ w_film,
                            const float* __restrict__ v_cond, const float* __restrict__ g_cond,
                            const float* __restrict__ b_cond, const float* __restrict__ cond_feats) {
    __shared__ float red[4];
    int blk = blockIdx.x, tid = threadIdx.x, lane = tid & 31, wid = tid >> 5;

    if (blk < 128) {
        int r = blk;
        float4 v4 = *(const float4*)(v_node + (size_t)r * NODE_DIM + tid * 4);
        float s = v4.x * v4.x + v4.y * v4.y + v4.z * v4.z + v4.w * v4.w;
        s = warp_red(s);
        if (lane == 0) red[wid] = s;
        __syncthreads();
        float scale = g_node[r] * rsqrtf(red[0] + red[1] + red[2] + red[3]);
        uint2 u;
        u.x = pk2h(v4.x * scale, v4.y * scale);
        u.y = pk2h(v4.z * scale, v4.w * scale);
        *(uint2*)(g_wn + (size_t)r * NODE_DIM + tid * 4) = u;
        float2 wf = *(const float2*)(w_film + (size_t)r * 256 + tid * 2);
        uint32_t h = pk2h(wf.x, wf.y);
        if (tid < 64)
            *(uint32_t*)(g_wcat + (size_t)r * 128 + tid * 2) = h;
        else
            *(uint32_t*)(g_wcat + (size_t)(128 + r) * 128 + tid * 2 - 128) = h;
    } else {
        int c = blk - 128;
        const float* vrow = v_cond + (size_t)c * COND_DIM;
        float4 v4 = *(const float4*)(vrow + tid * 4);
        float s = v4.x * v4.x + v4.y * v4.y + v4.z * v4.z + v4.w * v4.w;
        s = warp_red(s);
        if (lane == 0) red[wid] = s;
        __syncthreads();
        float scale = g_cond[c] * rsqrtf(red[0] + red[1] + red[2] + red[3]);
        float bc = b_cond[c];
        #pragma unroll
        for (int bb = 0; bb < 4; ++bb) {
            int b = wid * 4 + bb;
            const float* crow = cond_feats + (size_t)b * COND_DIM;
            float p = 0.f;
            #pragma unroll
            for (int t = 0; t < 4; ++t) {
                int k4 = (lane + t * 32) * 4;
                float4 cf = *(const float4*)(crow + k4);
                float4 vv = *(const float4*)(vrow + k4);
                p += cf.x * vv.x + cf.y * vv.y + cf.z * vv.z + cf.w * vv.w;
            }
            p = warp_red(p);
            if (lane == 0) g_gb[b * 2 * EDGE_DIM + c] = p * scale + bc;
        }
    }
    GRID_DEP_TRIGGER();   // outputs written; dependents may launch
}

// ---------------------------------------------------------------------------
// Fused GEMM (waits on prep; triggers film2 at end)
// ---------------------------------------------------------------------------
__global__ void __launch_bounds__(256, 1)
gemm_kernel(const float* __restrict__ node_feats, const float* __restrict__ b_node) {
    extern __shared__ char smem[];
    uint32_t sb = smem_to_u32(smem);
    int tid = threadIdx.x, wid = tid >> 5, lane = tid & 31;
    int tile = blockIdx.x;
    float* bn_s = (float*)(smem + GS_BN);
    if (tid < 128) bn_s[tid] = b_node[tid];

    const int m0 = (wid & 1) * 32;
    const int n1 = (wid >> 1) * 32;
    uint32_t aB1[2], bB1[2];
    #pragma unroll
    for (int mi = 0; mi < 2; ++mi)
        aB1[mi] = sb + GS_R0 + (m0 + mi * 16 + (lane & 15)) * 528 + ((lane >> 4) << 4);
    #pragma unroll
    for (int nb = 0; nb < 2; ++nb)
        bB1[nb] = sb + GS_R1 + (n1 + nb * 16 + ((lane >> 4) << 3) + (lane & 7)) * 528
                  + (((lane >> 3) & 1) << 4);

    float acc1[2][4][4];
    #pragma unroll
    for (int mi = 0; mi < 2; ++mi)
        #pragma unroll
        for (int ni = 0; ni < 4; ++ni)
            #pragma unroll
            for (int j = 0; j < 4; ++j) acc1[mi][ni][j] = 0.f;

    for (int p = 0; p < 2; ++p) {
        __syncthreads();
        // A: node_feats (input; independent of prep)
        for (int idx = tid; idx < 2048; idx += 256) {
            int r = idx >> 5, cc = idx & 31;
            const float* s = node_feats + (size_t)(tile * M_G + r) * NODE_DIM + p * 256 + cc * 8;
            float4 f0 = *(const float4*)s;
            float4 f1 = *(const float4*)(s + 4);
            uint4 u;
            u.x = pk2h(f0.x, f0.y); u.y = pk2h(f0.z, f0.w);
            u.z = pk2h(f1.x, f1.y); u.w = pk2h(f1.z, f1.w);
            *(uint4*)(smem + GS_R0 + r * 528 + cc * 16) = u;
        }
        if (p == 0) GRID_DEP_WAIT();   // prep outputs valid after this
        // B: g_wn (prep output)
        for (int idx = tid; idx < 4096; idx += 256) {
            int r = idx >> 5, cc = idx & 31;
            const uint4 wv = *(const uint4*)(g_wn + (size_t)r * NODE_DIM + p * 256 + cc * 8);
            *(uint4*)(smem + GS_R1 + r * 528 + cc * 16) = wv;
        }
        __syncthreads();
        #pragma unroll 4
        for (int kk = 0; kk < 16; ++kk) {
            uint32_t a[2][4], bf[2][4];
            #pragma unroll
            for (int mi = 0; mi < 2; ++mi)
                LDSM_X4(a[mi][0], a[mi][1], a[mi][2], a[mi][3], aB1[mi] + kk * 32);
            #pragma unroll
            for (int nb = 0; nb < 2; ++nb)
                LDSM_X4(bf[nb][0], bf[nb][1], bf[nb][2], bf[nb][3], bB1[nb] + kk * 32);
            #pragma unroll
            for (int mi = 0; mi < 2; ++mi)
                #pragma unroll
                for (int ni = 0; ni < 4; ++ni)
                    MMA16816(acc1[mi][ni], a[mi][0], a[mi][1], a[mi][2], a[mi][3],
                             bf[ni >> 1][(ni & 1) * 2], bf[ni >> 1][(ni & 1) * 2 + 1]);
        }
    }
    __syncthreads();

    // nodes (relu+bias fp16) -> region0; wcat -> region1
    {
        int rb = m0 + (lane >> 2);
        int cb = n1 + 2 * (lane & 3);
        #pragma unroll
        for (int mi = 0; mi < 2; ++mi)
            #pragma unroll
            for (int ni = 0; ni < 4; ++ni) {
                int r = rb + mi * 16;
                int c = cb + ni * 8;
                float b0 = bn_s[c], b1 = bn_s[c + 1];
                *(uint32_t*)(smem + GS_R0 + r * 272 + c * 2) =
                    pk2h(fmaxf(acc1[mi][ni][0] + b0, 0.f), fmaxf(acc1[mi][ni][1] + b1, 0.f));
                *(uint32_t*)(smem + GS_R0 + (r + 8) * 272 + c * 2) =
                    pk2h(fmaxf(acc1[mi][ni][2] + b0, 0.f), fmaxf(acc1[mi][ni][3] + b1, 0.f));
            }
    }
    for (int idx = tid; idx < 4096; idx += 256) {
        int r = idx >> 4, cc = idx & 15;
        const uint4 wv = *(const uint4*)(g_wcat + (size_t)r * 128 + cc * 8);
        *(uint4*)(smem + GS_R1 + r * 272 + cc * 16) = wv;
    }
    __syncthreads();

    // phase 2: 64x256x128
    const int n2 = (wid >> 1) * 64;
    uint32_t aB2[2], bB2[4];
    #pragma unroll
    for (int mi = 0; mi < 2; ++mi)
        aB2[mi] = sb + GS_R0 + (m0 + mi * 16 + (lane & 15)) * 272 + ((lane >> 4) << 4);
    #pragma unroll
    for (int nb = 0; nb < 4; ++nb)
        bB2[nb] = sb + GS_R1 + (n2 + nb * 16 + ((lane >> 4) << 3) + (lane & 7)) * 272
                  + (((lane >> 3) & 1) << 4);

    float acc2[2][8][4];
    #pragma unroll
    for (int mi = 0; mi < 2; ++mi)
        #pragma unroll
        for (int ni = 0; ni < 8; ++ni)
            #pragma unroll
            for (int j = 0; j < 4; ++j) acc2[mi][ni][j] = 0.f;

    #pragma unroll 2
    for (int kk = 0; kk < 8; ++kk) {
        uint32_t a[2][4], bf[4][4];
        #pragma unroll
        for (int mi = 0; mi < 2; ++mi)
            LDSM_X4(a[mi][0], a[mi][1], a[mi][2], a[mi][3], aB2[mi] + kk * 32);
        #pragma unroll
        for (int nb = 0; nb < 4; ++nb)
            LDSM_X4(bf[nb][0], bf[nb][1], bf[nb][2], bf[nb][3], bB2[nb] + kk * 32);
        #pragma unroll
        for (int mi = 0; mi < 2; ++mi)
            #pragma unroll
            for (int ni = 0; ni < 8; ++ni)
                MMA16816(acc2[mi][ni], a[mi][0], a[mi][1], a[mi][2], a[mi][3],
                         bf[ni >> 1][(ni & 1) * 2], bf[ni >> 1][(ni & 1) * 2 + 1]);
    }

    // P tile (fp16) to global
    {
        int rb = m0 + (lane >> 2);
        int cb = n2 + 2 * (lane & 3);
        #pragma unroll
        for (int mi = 0; mi < 2; ++mi)
            #pragma unroll
            for (int ni = 0; ni < 8; ++ni) {
                int r = tile * M_G + rb + mi * 16;
                int c = cb + ni * 8;
                *(uint32_t*)(g_P + (size_t)r * 256 + c) =
                    pk2h(acc2[mi][ni][0], acc2[mi][ni][1]);
                *(uint32_t*)(g_P + (size_t)(r + 8) * 256 + c) =
                    pk2h(acc2[mi][ni][2], acc2[mi][ni][3]);
            }
    }
    GRID_DEP_TRIGGER();   // g_P written; film2 may proceed
}

// ---------------------------------------------------------------------------
// film2: warp-per-edge (coalesced), fp16 P reads, streaming stores
// ---------------------------------------------------------------------------
__global__ void __launch_bounds__(256)
film2_kernel(const int* __restrict__ eidx32, const float* __restrict__ b_film,
             float* __restrict__ out) {
    __shared__ int rowA_s[128], rowB_s[128];
    __shared__ __align__(16) float gam_s[128], bet_s[128], bf_s[128];
    int tid = threadIdx.x, wid = tid >> 5, lane = tid & 31;
    int tile = blockIdx.x;

    // prologue: inputs only (independent of gemm)
    if (tid < 128) {
        int stride = (eidx32[1] == 0 && eidx32[3] == 0 && eidx32[5] == 0) ? 2 : 1;
        int ei = eidx32[(size_t)(tile * 128 + tid) * stride];
        rowA_s[tid] = ei >> 8;
        rowB_s[tid] = ((ei >> 16) << 8) | (ei & 255);
        bf_s[tid] = b_film[tid];
    }
    GRID_DEP_WAIT();   // g_P / g_gb valid after this
    if (tid < 128) {
        int batch = tile >> 7;
        gam_s[tid] = g_gb[batch * 2 * EDGE_DIM + tid] + 1.0f;
        bet_s[tid] = g_gb[batch * 2 * EDGE_DIM + EDGE_DIM + tid];
    }
    __syncthreads();

    int c4 = lane * 4;
    float4 gam4 = *(const float4*)(gam_s + c4);
    float4 bet4 = *(const float4*)(bet_s + c4);
    float4 bf4  = *(const float4*)(bf_s + c4);

    #pragma unroll 2
    for (int k = 0; k < 16; ++k) {
        int e = (wid << 4) + k;
        int rA = rowA_s[e], rB = rowB_s[e];
        // fp16 rows: lane reads 4 halves (8B) from each; fully coalesced 256B/warp
        uint2 ua = __ldg((const uint2*)(g_P + (size_t)rA * 256 + c4));
        uint2 ub = __ldg((const uint2*)(g_P + (size_t)rB * 256 + 128 + c4));
        float2 a0 = __half22float2(*(__half2*)&ua.x);
        float2 a1 = __half22float2(*(__half2*)&ua.y);
        float2 b0 = __half22float2(*(__half2*)&ub.x);
        float2 b1 = __half22float2(*(__half2*)&ub.y);
        float x0 = a0.x + b0.x + bf4.x;
        float x1 = a0.y + b0.y + bf4.y;
        float x2 = a1.x + b1.x + bf4.z;
        float x3 = a1.y + b1.y + bf4.w;
        float s = x0 + x1 + x2 + x3;
        float q = x0 * x0 + x1 * x1 + x2 * x2 + x3 * x3;
        #pragma unroll
        for (int o = 16; o; o >>= 1) {
            s += __shfl_xor_sync(0xffffffffu, s, o);
            q += __shfl_xor_sync(0xffffffffu, q, o);
        }
        float mu = s * (1.f / 128.f);
        float var = q * (1.f / 128.f) - mu * mu;
        float ri = rsqrtf(fmaxf(var, 0.f) + LN_EPS);
        float4 o4;
        o4.x = fmaxf((x0 - mu) * ri * gam4.x + bet4.x, 0.f);
        o4.y = fmaxf((x1 - mu) * ri * gam4.y + bet4.y, 0.f);
        o4.z = fmaxf((x2 - mu) * ri * gam4.z + bet4.z, 0.f);
        o4.w = fmaxf((x3 - mu) * ri * gam4.w + bet4.w, 0.f);
        __stcs((float4*)(out + ((size_t)tile * 128 + e) * EDGE_DIM + c4), o4);
    }
}

// ---------------------------------------------------------------------------
// Launch (PDL chain with end-of-kernel triggers: prep -> gemm -> film2)
// ---------------------------------------------------------------------------
extern "C" void kernel_launch(void* const* d_in, const int* in_sizes, int n_in,
                              void* d_out, int out_size) {
    const float* node_feats = (const float*)d_in[0];
    const float* cond_feats = (const float*)d_in[1];
    const int*   eidx       = (const int*)d_in[2];
    const float* v_node     = (const float*)d_in[3];
    const float* g_node     = (const float*)d_in[4];
    const float* b_node     = (const float*)d_in[5];
    const float* v_cond     = (const float*)d_in[6];
    const float* g_cond     = (const float*)d_in[7];
    const float* b_cond     = (const float*)d_in[8];
    const float* w_film     = (const float*)d_in[9];
    const float* b_film     = (const float*)d_in[10];
    float* out = (float*)d_out;

    cudaFuncSetAttribute(gemm_kernel, cudaFuncAttributeMaxDynamicSharedMemorySize, SMEM_GEMM);

    prep_kernel<<<384, 128>>>(v_node, g_node, w_film, v_cond, g_cond, b_cond, cond_feats);

    cudaLaunchAttribute at[1];
    at[0].id = cudaLaunchAttributeProgrammaticStreamSerialization;
    at[0].val.programmaticStreamSerializationAllowed = 1;

    {
        cudaLaunchConfig_t cfg = {};
        cfg.gridDim = dim3(G_TILES);
        cfg.blockDim = dim3(256);
        cfg.dynamicSmemBytes = SMEM_GEMM;
        cfg.stream = 0;
        cfg.attrs = at;
        cfg.numAttrs = 1;
        cudaLaunchKernelEx(&cfg, gemm_kernel, node_feats, b_node);
    }
    {
        cudaLaunchConfig_t cfg = {};
        cfg.gridDim = dim3(FILM_TILES);
        cfg.blockDim = dim3(256);
        cfg.dynamicSmemBytes = 0;
        cfg.stream = 0;
        cfg.attrs = at;
        cfg.numAttrs = 1;
        cudaLaunchKernelEx(&cfg, film2_kernel, eidx, b_film, out);
    }
}